// round 3
// baseline (speedup 1.0000x reference)
#include <cuda_runtime.h>
#include <math.h>

#define T_    64
#define B_    512
#define NTOK  512
#define NINP  600
#define NHID  600
#define NB    6
#define TOPK_ 4
#define BS_   100
#define ATT   340
#define DK    64
#define DC    32

#define TB    (T_ * B_)              // 32768
#define DEC_OFF   (TB * NTOK)        // 16777216

typedef unsigned long long ull;

// ---------------- f32x2 packed helpers ----------------
__device__ __forceinline__ ull dup2(float x) {
    ull r; asm("mov.b64 %0, {%1, %1};" : "=l"(r) : "f"(x)); return r;
}
__device__ __forceinline__ void fma2(ull &d, ull a, ull b) {
    asm("fma.rn.f32x2 %0, %1, %2, %0;" : "+l"(d) : "l"(a), "l"(b));
}
__device__ __forceinline__ float lo2(ull v) {
    float x, y; asm("mov.b64 {%0, %1}, %2;" : "=f"(x), "=f"(y) : "l"(v)); return x;
}
__device__ __forceinline__ float hi2(ull v) {
    float x, y; asm("mov.b64 {%0, %1}, %2;" : "=f"(x), "=f"(y) : "l"(v)); return y;
}

// ---------------- scratch (device globals) ----------------
__device__ float g_T1[513 * 404];           // [enc_W;enc_b] @ [Wk | Wv]
__device__ float g_W12[513 * 400];          // folded [wqk (100) | vx (300)], row 512 = bias
__device__ float g_wqkvx[(size_t)TB * 400]; // per-(t,b): wqk (100) | vx (300)
__device__ float g_out[(size_t)TB * NHID];  // h history for dec GEMM
__device__ float g_WhT[300 * 100];          // Wh transposed (col-major rows, contiguous k)
__device__ float g_WqkvT[164 * 100];        // [Wq2|Wk2|Wv2] transposed

// ---------------- fold kernels ----------------
__global__ void fold1(const float* __restrict__ enc_W, const float* __restrict__ enc_b,
                      const float* __restrict__ Wk,    const float* __restrict__ Wv) {
    int idx = blockIdx.x * blockDim.x + threadIdx.x;
    if (idx >= 513 * 404) return;
    int r = idx / 404, c = idx % 404;
    const float* arow = (r < 512) ? (enc_W + (size_t)r * NINP) : enc_b;
    float acc = 0.f;
    if (c < 64) {
        #pragma unroll 4
        for (int k = 0; k < NINP; k++) acc += arow[k] * __ldg(&Wk[k * DK + c]);
    } else {
        int cc = c - 64;
        #pragma unroll 4
        for (int k = 0; k < NINP; k++) acc += arow[k] * __ldg(&Wv[k * ATT + cc]);
    }
    g_T1[idx] = acc;
}

__global__ void fold2(const float* __restrict__ Wq, const float* __restrict__ Wx) {
    int idx = blockIdx.x * blockDim.x + threadIdx.x;
    if (idx >= 513 * 400) return;
    int r = idx / 400, c = idx % 400;
    float acc = 0.f;
    if (c < 100) {
        const float* t1 = g_T1 + r * 404;
        const float* wq = Wq + c * DK;
        #pragma unroll 8
        for (int k = 0; k < DK; k++) acc += t1[k] * wq[k];
    } else {
        const float* t1 = g_T1 + r * 404 + 64;
        int cc = c - 100;
        #pragma unroll 4
        for (int k = 0; k < ATT; k++) acc += t1[k] * __ldg(&Wx[k * 300 + cc]);
    }
    g_W12[idx] = acc;
}

// transpose step weights: WhT[c][k] = Wh[k][c]; WqkvT[c][k] = [Wq2|Wk2|Wv2][k][c]
__global__ void transposeW(const float* __restrict__ Wh,
                           const float* __restrict__ Wq2,
                           const float* __restrict__ Wk2,
                           const float* __restrict__ Wv2) {
    int i = blockIdx.x * blockDim.x + threadIdx.x;
    if (i < 300 * 100) {
        int c = i / 100, k = i % 100;
        g_WhT[i] = Wh[k * 300 + c];
    } else if (i < 300 * 100 + 164 * 100) {
        int j = i - 300 * 100;
        int c = j / 100, k = j % 100;
        float v;
        if (c < 32)      v = Wq2[k * 32 + c];
        else if (c < 64) v = Wk2[k * 32 + (c - 32)];
        else             v = Wv2[k * 100 + (c - 64)];
        g_WqkvT[j] = v;
    }
}

// ---------------- fp32 SGEMM with f32x2: C = A@B + bias ----------------
__device__ __forceinline__ void sgemm_body(
    const float* __restrict__ A, const float* __restrict__ B,
    const float* __restrict__ bias, float* __restrict__ C,
    int M, int N, int K)
{
    __shared__ __align__(16) float As[8][128];
    __shared__ __align__(16) float Bs[8][128];
    const int tid = threadIdx.x;
    const int m0 = blockIdx.y * 128;
    const int n0 = blockIdx.x * 128;
    const int arow = tid >> 1, acol = (tid & 1) * 4;
    const int brow = tid >> 5, bcol = (tid & 31) * 4;
    const int tm = (tid >> 4) * 8, tn = (tid & 15) * 8;

    ull acc2[8][4];
    #pragma unroll
    for (int i = 0; i < 8; i++)
        #pragma unroll
        for (int j = 0; j < 4; j++) acc2[i][j] = 0ull;

    for (int k0 = 0; k0 < K; k0 += 8) {
        float4 av = *(const float4*)(A + (size_t)(m0 + arow) * K + k0 + acol);
        As[acol + 0][arow] = av.x;
        As[acol + 1][arow] = av.y;
        As[acol + 2][arow] = av.z;
        As[acol + 3][arow] = av.w;
        float4 bv = make_float4(0.f, 0.f, 0.f, 0.f);
        if (n0 + bcol < N)
            bv = *(const float4*)(B + (size_t)(k0 + brow) * N + n0 + bcol);
        *(float4*)&Bs[brow][bcol] = bv;
        __syncthreads();
        #pragma unroll
        for (int k = 0; k < 8; k++) {
            float4 a0 = *(const float4*)&As[k][tm];
            float4 a1 = *(const float4*)&As[k][tm + 4];
            ulonglong2 b01 = *(const ulonglong2*)&Bs[k][tn];
            ulonglong2 b23 = *(const ulonglong2*)&Bs[k][tn + 4];
            ull bp0 = b01.x, bp1 = b01.y, bp2 = b23.x, bp3 = b23.y;
            ull ad[8];
            ad[0] = dup2(a0.x); ad[1] = dup2(a0.y); ad[2] = dup2(a0.z); ad[3] = dup2(a0.w);
            ad[4] = dup2(a1.x); ad[5] = dup2(a1.y); ad[6] = dup2(a1.z); ad[7] = dup2(a1.w);
            #pragma unroll
            for (int i = 0; i < 8; i++) {
                fma2(acc2[i][0], ad[i], bp0);
                fma2(acc2[i][1], ad[i], bp1);
                fma2(acc2[i][2], ad[i], bp2);
                fma2(acc2[i][3], ad[i], bp3);
            }
        }
        __syncthreads();
    }
    #pragma unroll
    for (int i = 0; i < 8; i++) {
        int m = m0 + tm + i;
        #pragma unroll
        for (int j2 = 0; j2 < 4; j2++) {
            int n = n0 + tn + j2 * 2;
            if (n < N) {
                float2 v;
                v.x = lo2(acc2[i][j2]) + bias[n + 0];
                v.y = hi2(acc2[i][j2]) + bias[n + 1];
                *(float2*)(C + (size_t)m * N + n) = v;
            }
        }
    }
}

__global__ __launch_bounds__(256) void gemm_wqkvx(const float* __restrict__ input) {
    sgemm_body(input, g_W12, g_W12 + 512 * 400, g_wqkvx, TB, 400, NTOK);
}

__global__ __launch_bounds__(256) void gemm_dec(const float* __restrict__ dec_W,
                                                const float* __restrict__ dec_b,
                                                float* __restrict__ C) {
    sgemm_body(g_out, dec_W, dec_b, C, TB, NTOK, NHID);
}

// ---------------- persistent recurrent kernel: 2 batches/block, all 64 steps ----
// State layout: hb_t[k][slot] (k-major), slot = bb*6 + n, rows padded to 16.
__global__ __launch_bounds__(320, 2) void steps_persistent(
    const float* __restrict__ hidden,
    const float* __restrict__ masks,
    const float* __restrict__ gru_b,
    float* __restrict__ hT_out,
    float* __restrict__ bmask_out)
{
    __shared__ __align__(16) float hb_t[100][16];
    __shared__ __align__(16) float hn_t[100][16];
    __shared__ float hg[12][300];
    __shared__ float wqk_s[2][100];
    __shared__ float vx_s[2][300];
    __shared__ float sarr[12], parr[12], bm[12];
    __shared__ float q2[12][32], k2[12][32], v2[12][100];
    __shared__ float p2[12][6];

    const int tid = threadIdx.x;
    const int b0 = blockIdx.x * 2;

    // initial state load (coalesced global; one-time smem conflicts OK)
    for (int i = tid; i < 1200; i += 320) {
        int bb = i / 600, j = i % 600;
        hb_t[j % 100][bb * 6 + j / 100] = hidden[(b0 + bb) * NHID + j];
    }

    for (int t = 0; t < T_; t++) {
        __syncthreads();

        // phase 0: mask state in place + load folded inputs
        {
            float m0v = masks[t * B_ + b0];
            float m1v = masks[t * B_ + b0 + 1];
            for (int i = tid; i < 1200; i += 320) {
                int jj = i / 12, s = i % 12;
                hb_t[jj][s] *= (s < 6) ? m0v : m1v;
            }
        }
        for (int i = tid; i < 800; i += 320) {
            int bb = i / 400, c = i % 400;
            float v = g_wqkvx[(size_t)(t * B_ + b0 + bb) * 400 + c];
            if (c < 100) wqk_s[bb][c] = v; else vx_s[bb][c - 100] = v;
        }
        __syncthreads();

        // phase 1: s[u] = sc1 * <hb[:,u], wqk>, p1 = sigmoid(s). 16 threads/slot.
        if (tid < 192) {
            int u = tid >> 4, l = tid & 15;
            const float* w = wqk_s[u / 6];
            float s = 0.f;
            for (int k = l; k < 100; k += 16) s += hb_t[k][u] * w[k];
            s += __shfl_down_sync(0xffffffff, s, 8, 16);
            s += __shfl_down_sync(0xffffffff, s, 4, 16);
            s += __shfl_down_sync(0xffffffff, s, 2, 16);
            s += __shfl_down_sync(0xffffffff, s, 1, 16);
            if (l == 0) {
                s *= 0.125f;
                sarr[u] = s;
                parr[u] = 1.f / (1.f + expf(-s));
            }
        }
        __syncthreads();

        // phase 2 (threads 0..11): top-4-of-6 mask
        if (tid < 12) {
            int bb = tid / 6, n = tid % 6;
            float sn = sarr[tid];
            int cnt = 0;
            #pragma unroll
            for (int m = 0; m < 6; m++) {
                float sm = sarr[bb * 6 + m];
                if (sm > sn || (sm == sn && m < n)) cnt++;
            }
            float v = (cnt < TOPK_) ? 1.f : 0.f;
            bm[tid] = v;
            bmask_out[(size_t)t * B_ * NB + (b0 + bb) * NB + n] = v;
        }
        // phase 3 (concurrent, threads 0..299): hg = hb @ Wh, f32x2 packed
        if (tid < 300) {
            ull acc[6] = {0, 0, 0, 0, 0, 0};
            const float* wt = g_WhT + tid * 100;
            for (int k = 0; k < 100; k += 4) {
                float4 wv = *(const float4*)(wt + k);
                #pragma unroll
                for (int kk = 0; kk < 4; kk++) {
                    float w = (kk == 0) ? wv.x : (kk == 1) ? wv.y : (kk == 2) ? wv.z : wv.w;
                    ull wd = dup2(w);
                    const ulonglong2* hr = (const ulonglong2*)&hb_t[k + kk][0];
                    ulonglong2 h01 = hr[0];
                    ulonglong2 h23 = hr[1];
                    ulonglong2 h45 = hr[2];
                    fma2(acc[0], h01.x, wd); fma2(acc[1], h01.y, wd);
                    fma2(acc[2], h23.x, wd); fma2(acc[3], h23.y, wd);
                    fma2(acc[4], h45.x, wd); fma2(acc[5], h45.y, wd);
                }
            }
            #pragma unroll
            for (int p = 0; p < 6; p++) {
                hg[2 * p][tid]     = lo2(acc[p]);
                hg[2 * p + 1][tid] = hi2(acc[p]);
            }
        }
        __syncthreads();

        // phase 4: GRU gates
        for (int i = tid; i < 1200; i += 320) {
            int u = i / 100, j = i % 100;
            int bb = u / 6;
            float p = parr[u];
            float xr = p * vx_s[bb][j]       + gru_b[j];
            float xz = p * vx_s[bb][j + 100] + gru_b[j + 100];
            float xn = p * vx_s[bb][j + 200] + gru_b[j + 200];
            float r  = 1.f / (1.f + expf(-(xr + hg[u][j])));
            float z  = 1.f / (1.f + expf(-(xz + hg[u][j + 100])));
            float nn = tanhf(xn + r * hg[u][j + 200]);
            hn_t[j][u] = (1.f - z) * nn + z * hb_t[j][u];
        }
        __syncthreads();

        // phase 5: q2/k2/v2 = hn @ [Wq2 | Wk2 | Wv2], f32x2 packed
        if (tid < 164) {
            ull acc[6] = {0, 0, 0, 0, 0, 0};
            const float* wt = g_WqkvT + tid * 100;
            for (int k = 0; k < 100; k += 4) {
                float4 wv = *(const float4*)(wt + k);
                #pragma unroll
                for (int kk = 0; kk < 4; kk++) {
                    float w = (kk == 0) ? wv.x : (kk == 1) ? wv.y : (kk == 2) ? wv.z : wv.w;
                    ull wd = dup2(w);
                    const ulonglong2* hr = (const ulonglong2*)&hn_t[k + kk][0];
                    ulonglong2 h01 = hr[0];
                    ulonglong2 h23 = hr[1];
                    ulonglong2 h45 = hr[2];
                    fma2(acc[0], h01.x, wd); fma2(acc[1], h01.y, wd);
                    fma2(acc[2], h23.x, wd); fma2(acc[3], h23.y, wd);
                    fma2(acc[4], h45.x, wd); fma2(acc[5], h45.y, wd);
                }
            }
            #pragma unroll
            for (int p = 0; p < 6; p++) {
                float x = lo2(acc[p]), y = hi2(acc[p]);
                if (tid < 32) {
                    q2[2 * p][tid] = x; q2[2 * p + 1][tid] = y;
                } else if (tid < 64) {
                    k2[2 * p][tid - 32] = x; k2[2 * p + 1][tid - 32] = y;
                } else {
                    v2[2 * p][tid - 64] = x; v2[2 * p + 1][tid - 64] = y;
                }
            }
        }
        __syncthreads();

        // phase 6: attention-2 scores (6x6 per batch)
        if (tid < 72) {
            int bb = tid / 36, nm = tid % 36;
            int n = nm / 6, m = nm % 6;
            const float* qr = q2[bb * 6 + n];
            const float* kr = k2[bb * 6 + m];
            float s = 0.f;
            #pragma unroll
            for (int d = 0; d < 32; d++) s += qr[d] * kr[d];
            p2[bb * 6 + n][m] = s * 0.17677669529663687f;
        }
        __syncthreads();

        // phase 7: softmax over m
        if (tid < 12) {
            float mx = -1e30f;
            #pragma unroll
            for (int m = 0; m < 6; m++) mx = fmaxf(mx, p2[tid][m]);
            float e[6], sum = 0.f;
            #pragma unroll
            for (int m = 0; m < 6; m++) { e[m] = expf(p2[tid][m] - mx); sum += e[m]; }
            float inv = 1.f / sum;
            #pragma unroll
            for (int m = 0; m < 6; m++) p2[tid][m] = e[m] * inv;
        }
        __syncthreads();

        // phase 8: hc = hn + p2@v2; blend by bmask; write history + state
        for (int i = tid; i < 1200; i += 320) {
            int u = i / 100, j = i % 100;
            int bb = u / 6;
            float acc = hn_t[j][u];
            #pragma unroll
            for (int m = 0; m < 6; m++) acc += p2[u][m] * v2[bb * 6 + m][j];
            float res = (bm[u] > 0.5f) ? acc : hb_t[j][u];
            hb_t[j][u] = res;
            int b = b0 + bb;
            int col = (u % 6) * 100 + j;
            g_out[((size_t)t * B_ + b) * NHID + col] = res;
        }
    }

    __syncthreads();
    for (int i = tid; i < 1200; i += 320) {
        int bb = i / 600, j = i % 600;
        hT_out[(b0 + bb) * NHID + j] = hb_t[j % 100][bb * 6 + j / 100];
    }
}

// ---------------- launch ----------------
extern "C" void kernel_launch(void* const* d_in, const int* in_sizes, int n_in,
                              void* d_out, int out_size) {
    const float* input  = (const float*)d_in[0];
    const float* hidden = (const float*)d_in[1];
    const float* masks  = (const float*)d_in[2];
    const float* enc_W  = (const float*)d_in[3];
    const float* enc_b  = (const float*)d_in[4];
    const float* Wq     = (const float*)d_in[5];
    const float* Wk     = (const float*)d_in[6];
    const float* Wv     = (const float*)d_in[7];
    const float* Wx     = (const float*)d_in[8];
    const float* Wh     = (const float*)d_in[9];
    const float* gru_b  = (const float*)d_in[10];
    const float* Wq2    = (const float*)d_in[11];
    const float* Wk2    = (const float*)d_in[12];
    const float* Wv2    = (const float*)d_in[13];
    const float* dec_W  = (const float*)d_in[14];
    const float* dec_b  = (const float*)d_in[15];
    float* out = (float*)d_out;

    fold1<<<(513 * 404 + 255) / 256, 256>>>(enc_W, enc_b, Wk, Wv);
    fold2<<<(513 * 400 + 255) / 256, 256>>>(Wq, Wx);
    transposeW<<<(300 * 100 + 164 * 100 + 255) / 256, 256>>>(Wh, Wq2, Wk2, Wv2);

    gemm_wqkvx<<<dim3((400 + 127) / 128, TB / 128), 256>>>(input);

    float* hT_out    = out + DEC_OFF;
    float* bmask_out = out + DEC_OFF + B_ * NHID;
    steps_persistent<<<B_ / 2, 320>>>(hidden, masks, gru_b, hT_out, bmask_out);

    gemm_dec<<<dim3((NTOK + 127) / 128, TB / 128), 256>>>(dec_W, dec_b, out);
}

// round 4
// speedup vs baseline: 1.0400x; 1.0400x over previous
#include <cuda_runtime.h>
#include <math.h>

#define T_    64
#define B_    512
#define NTOK  512
#define NINP  600
#define NHID  600
#define NB    6
#define TOPK_ 4
#define BS_   100
#define ATT   340
#define DK    64
#define DC    32

#define TB    (T_ * B_)              // 32768
#define DEC_OFF   (TB * NTOK)        // 16777216

typedef unsigned long long ull;

// ---------------- f32x2 packed helpers ----------------
__device__ __forceinline__ ull dup2(float x) {
    ull r; asm("mov.b64 %0, {%1, %1};" : "=l"(r) : "f"(x)); return r;
}
__device__ __forceinline__ void fma2(ull &d, ull a, ull b) {
    asm("fma.rn.f32x2 %0, %1, %2, %0;" : "+l"(d) : "l"(a), "l"(b));
}
__device__ __forceinline__ float lo2(ull v) {
    float x, y; asm("mov.b64 {%0, %1}, %2;" : "=f"(x), "=f"(y) : "l"(v)); return x;
}
__device__ __forceinline__ float hi2(ull v) {
    float x, y; asm("mov.b64 {%0, %1}, %2;" : "=f"(x), "=f"(y) : "l"(v)); return y;
}

// ---------------- scratch (device globals) ----------------
__device__ float g_T1[513 * 404];
__device__ float g_W12[513 * 400];
__device__ float g_wqkvx[(size_t)TB * 400];
__device__ float g_out[(size_t)TB * NHID];
__device__ float g_WhT[300 * 100];          // WhT[c][k] contiguous k
__device__ float g_WqkvT[164 * 100];        // [Wq2|Wk2|Wv2]^T, contiguous k

// ---------------- fold kernels ----------------
__global__ void fold1(const float* __restrict__ enc_W, const float* __restrict__ enc_b,
                      const float* __restrict__ Wk,    const float* __restrict__ Wv) {
    int idx = blockIdx.x * blockDim.x + threadIdx.x;
    if (idx >= 513 * 404) return;
    int r = idx / 404, c = idx % 404;
    const float* arow = (r < 512) ? (enc_W + (size_t)r * NINP) : enc_b;
    float acc = 0.f;
    if (c < 64) {
        #pragma unroll 4
        for (int k = 0; k < NINP; k++) acc += arow[k] * __ldg(&Wk[k * DK + c]);
    } else {
        int cc = c - 64;
        #pragma unroll 4
        for (int k = 0; k < NINP; k++) acc += arow[k] * __ldg(&Wv[k * ATT + cc]);
    }
    g_T1[idx] = acc;
}

__global__ void fold2(const float* __restrict__ Wq, const float* __restrict__ Wx) {
    int idx = blockIdx.x * blockDim.x + threadIdx.x;
    if (idx >= 513 * 400) return;
    int r = idx / 400, c = idx % 400;
    float acc = 0.f;
    if (c < 100) {
        const float* t1 = g_T1 + r * 404;
        const float* wq = Wq + c * DK;
        #pragma unroll 8
        for (int k = 0; k < DK; k++) acc += t1[k] * wq[k];
    } else {
        const float* t1 = g_T1 + r * 404 + 64;
        int cc = c - 100;
        #pragma unroll 4
        for (int k = 0; k < ATT; k++) acc += t1[k] * __ldg(&Wx[k * 300 + cc]);
    }
    g_W12[idx] = acc;
}

__global__ void transposeW(const float* __restrict__ Wh,
                           const float* __restrict__ Wq2,
                           const float* __restrict__ Wk2,
                           const float* __restrict__ Wv2) {
    int i = blockIdx.x * blockDim.x + threadIdx.x;
    if (i < 300 * 100) {
        int c = i / 100, k = i % 100;
        g_WhT[i] = Wh[k * 300 + c];
    } else if (i < 300 * 100 + 164 * 100) {
        int j = i - 300 * 100;
        int c = j / 100, k = j % 100;
        float v;
        if (c < 32)      v = Wq2[k * 32 + c];
        else if (c < 64) v = Wk2[k * 32 + (c - 32)];
        else             v = Wv2[k * 100 + (c - 64)];
        g_WqkvT[j] = v;
    }
}

// ---------------- fp32 SGEMM (f32x2): C = A@B + bias ----------------
__device__ __forceinline__ void sgemm_body(
    const float* __restrict__ A, const float* __restrict__ B,
    const float* __restrict__ bias, float* __restrict__ C,
    int M, int N, int K)
{
    __shared__ __align__(16) float As[8][128];
    __shared__ __align__(16) float Bs[8][128];
    const int tid = threadIdx.x;
    const int m0 = blockIdx.y * 128;
    const int n0 = blockIdx.x * 128;
    const int arow = tid >> 1, acol = (tid & 1) * 4;
    const int brow = tid >> 5, bcol = (tid & 31) * 4;
    const int tm = (tid >> 4) * 8, tn = (tid & 15) * 8;

    ull acc2[8][4];
    #pragma unroll
    for (int i = 0; i < 8; i++)
        #pragma unroll
        for (int j = 0; j < 4; j++) acc2[i][j] = 0ull;

    for (int k0 = 0; k0 < K; k0 += 8) {
        float4 av = *(const float4*)(A + (size_t)(m0 + arow) * K + k0 + acol);
        As[acol + 0][arow] = av.x;
        As[acol + 1][arow] = av.y;
        As[acol + 2][arow] = av.z;
        As[acol + 3][arow] = av.w;
        float4 bv = make_float4(0.f, 0.f, 0.f, 0.f);
        if (n0 + bcol < N)
            bv = *(const float4*)(B + (size_t)(k0 + brow) * N + n0 + bcol);
        *(float4*)&Bs[brow][bcol] = bv;
        __syncthreads();
        #pragma unroll
        for (int k = 0; k < 8; k++) {
            float4 a0 = *(const float4*)&As[k][tm];
            float4 a1 = *(const float4*)&As[k][tm + 4];
            ulonglong2 b01 = *(const ulonglong2*)&Bs[k][tn];
            ulonglong2 b23 = *(const ulonglong2*)&Bs[k][tn + 4];
            ull ad[8];
            ad[0] = dup2(a0.x); ad[1] = dup2(a0.y); ad[2] = dup2(a0.z); ad[3] = dup2(a0.w);
            ad[4] = dup2(a1.x); ad[5] = dup2(a1.y); ad[6] = dup2(a1.z); ad[7] = dup2(a1.w);
            #pragma unroll
            for (int i = 0; i < 8; i++) {
                fma2(acc2[i][0], ad[i], b01.x);
                fma2(acc2[i][1], ad[i], b01.y);
                fma2(acc2[i][2], ad[i], b23.x);
                fma2(acc2[i][3], ad[i], b23.y);
            }
        }
        __syncthreads();
    }
    #pragma unroll
    for (int i = 0; i < 8; i++) {
        int m = m0 + tm + i;
        #pragma unroll
        for (int j2 = 0; j2 < 4; j2++) {
            int n = n0 + tn + j2 * 2;
            if (n < N) {
                float2 v;
                v.x = lo2(acc2[i][j2]) + bias[n + 0];
                v.y = hi2(acc2[i][j2]) + bias[n + 1];
                *(float2*)(C + (size_t)m * N + n) = v;
            }
        }
    }
}

__global__ __launch_bounds__(256) void gemm_wqkvx(const float* __restrict__ input) {
    sgemm_body(input, g_W12, g_W12 + 512 * 400, g_wqkvx, TB, 400, NTOK);
}

__global__ __launch_bounds__(256) void gemm_dec(const float* __restrict__ dec_W,
                                                const float* __restrict__ dec_b,
                                                float* __restrict__ C) {
    sgemm_body(g_out, dec_W, dec_b, C, TB, NTOK, NHID);
}

// ---------------- persistent steps: 4 batches/block, grid 128, 640 threads ----
struct StepSmem {
    float hb[100][32];     // k-major state, slots 0..23 (u = bb*6+n)
    float hn[100][32];
    float hg[24][301];     // raw (unmasked) hb@Wh, pitch 301 (conflict-free)
    float wqk[4][100];
    float vx[4][300];
    float sarr[24], parr[24], bm[24];
    float q2[24][33], k2[24][33];
    float v2[24][101];
    float p2[24][8];
};

__global__ __launch_bounds__(640, 1) void steps_persistent(
    const float* __restrict__ hidden,
    const float* __restrict__ masks,
    const float* __restrict__ gru_b,
    float* __restrict__ hT_out,
    float* __restrict__ bmask_out)
{
    extern __shared__ __align__(16) char smem_raw[];
    StepSmem& s = *reinterpret_cast<StepSmem*>(smem_raw);

    const int tid = threadIdx.x;
    const int b0 = blockIdx.x * 4;

    // initial state load: hb[k][u], u = bb*6 + n, element = hidden[b][n*100+k]
    for (int i = tid; i < 2400; i += 640) {
        int bb = i / 600, j = i % 600;
        s.hb[j % 100][bb * 6 + j / 100] = hidden[(b0 + bb) * NHID + j];
    }

    for (int t = 0; t < T_; t++) {
        __syncthreads();   // b1: previous phase F complete, hb final

        // ---- interval 1 (concurrent): hg = hb@Wh  |  warp19: prefetch+scores+topk
        if (tid < 600) {
            const int col = (tid < 300) ? tid : tid - 300;
            const int g   = (tid < 300) ? 0 : 12;
            ull acc[6] = {0, 0, 0, 0, 0, 0};
            const float* wt = g_WhT + col * 100;
            for (int k = 0; k < 100; k += 4) {
                float4 wv = *(const float4*)(wt + k);
                #pragma unroll
                for (int kk = 0; kk < 4; kk++) {
                    float w = (kk == 0) ? wv.x : (kk == 1) ? wv.y : (kk == 2) ? wv.z : wv.w;
                    ull wd = dup2(w);
                    const ulonglong2* hr = (const ulonglong2*)&s.hb[k + kk][g];
                    ulonglong2 h01 = hr[0], h23 = hr[1], h45 = hr[2];
                    fma2(acc[0], h01.x, wd); fma2(acc[1], h01.y, wd);
                    fma2(acc[2], h23.x, wd); fma2(acc[3], h23.y, wd);
                    fma2(acc[4], h45.x, wd); fma2(acc[5], h45.y, wd);
                }
            }
            #pragma unroll
            for (int p = 0; p < 6; p++) {
                s.hg[g + 2 * p][col]     = lo2(acc[p]);
                s.hg[g + 2 * p + 1][col] = hi2(acc[p]);
            }
        } else if (tid >= 608) {
            const int lane = tid - 608;
            // prefetch wqk (4x100) and vx (4x300) as float4
            const float* src = g_wqkvx + (size_t)(t * B_ + b0) * 400;
            for (int j = lane; j < 100; j += 32) {
                int bb = j / 25, c4 = j % 25;
                *(float4*)&s.wqk[bb][c4 * 4] = *(const float4*)(src + bb * 400 + c4 * 4);
            }
            for (int j = lane; j < 300; j += 32) {
                int bb = j / 75, c4 = j % 75;
                *(float4*)&s.vx[bb][c4 * 4] = *(const float4*)(src + bb * 400 + 100 + c4 * 4);
            }
            __syncwarp();
            if (lane < 24) {
                const int u = lane, bb = u / 6;
                const float m = masks[t * B_ + b0 + bb];
                const float* w = s.wqk[bb];
                float sc = 0.f;
                #pragma unroll 4
                for (int k = 0; k < 100; k++) sc += s.hb[k][u] * w[k];
                sc *= 0.125f * m;                 // mask folded (scalar commutes)
                s.sarr[u] = sc;
                s.parr[u] = 1.f / (1.f + expf(-sc));
            }
            __syncwarp();
            if (lane < 24) {
                const int u = lane, bb = u / 6, n = u % 6;
                float sn = s.sarr[u];
                int cnt = 0;
                #pragma unroll
                for (int m2 = 0; m2 < 6; m2++) {
                    float sm = s.sarr[bb * 6 + m2];
                    if (sm > sn || (sm == sn && m2 < n)) cnt++;
                }
                float v = (cnt < TOPK_) ? 1.f : 0.f;
                s.bm[u] = v;
                bmask_out[(size_t)t * B_ * NB + (b0 + bb) * NB + n] = v;
            }
        }
        __syncthreads();   // b2: hg, parr, wqk/vx, bm ready

        // ---- phase C: GRU gates -> hn (mask applied to hg and hb here)
        {
            const int u = tid & 31, jb = tid >> 5;     // 20 j-slices
            if (u < 24) {
                const int bb = u / 6;
                const float m = masks[t * B_ + b0 + bb];
                const float p = s.parr[u];
                for (int j = jb; j < 100; j += 20) {
                    float xr = p * s.vx[bb][j]       + gru_b[j];
                    float xz = p * s.vx[bb][j + 100] + gru_b[j + 100];
                    float xn = p * s.vx[bb][j + 200] + gru_b[j + 200];
                    float r  = 1.f / (1.f + expf(-(xr + m * s.hg[u][j])));
                    float z  = 1.f / (1.f + expf(-(xz + m * s.hg[u][j + 100])));
                    float nn = tanhf(xn + r * (m * s.hg[u][j + 200]));
                    s.hn[j][u] = (1.f - z) * nn + z * (m * s.hb[j][u]);
                }
            }
        }
        __syncthreads();   // b3: hn ready

        // ---- phase D: q2/k2/v2 = hn @ [Wq2|Wk2|Wv2]
        if (tid < 328) {
            const int col = (tid < 164) ? tid : tid - 164;
            const int g   = (tid < 164) ? 0 : 12;
            ull acc[6] = {0, 0, 0, 0, 0, 0};
            const float* wt = g_WqkvT + col * 100;
            for (int k = 0; k < 100; k += 4) {
                float4 wv = *(const float4*)(wt + k);
                #pragma unroll
                for (int kk = 0; kk < 4; kk++) {
                    float w = (kk == 0) ? wv.x : (kk == 1) ? wv.y : (kk == 2) ? wv.z : wv.w;
                    ull wd = dup2(w);
                    const ulonglong2* hr = (const ulonglong2*)&s.hn[k + kk][g];
                    ulonglong2 h01 = hr[0], h23 = hr[1], h45 = hr[2];
                    fma2(acc[0], h01.x, wd); fma2(acc[1], h01.y, wd);
                    fma2(acc[2], h23.x, wd); fma2(acc[3], h23.y, wd);
                    fma2(acc[4], h45.x, wd); fma2(acc[5], h45.y, wd);
                }
            }
            #pragma unroll
            for (int p = 0; p < 6; p++) {
                float x = lo2(acc[p]), y = hi2(acc[p]);
                int u0 = g + 2 * p, u1 = g + 2 * p + 1;
                if (col < 32)      { s.q2[u0][col] = x;      s.q2[u1][col] = y; }
                else if (col < 64) { s.k2[u0][col - 32] = x; s.k2[u1][col - 32] = y; }
                else               { s.v2[u0][col - 64] = x; s.v2[u1][col - 64] = y; }
            }
        }
        __syncthreads();   // b4: q2/k2/v2 ready

        // ---- phase E: attention-2 scores + softmax (warp per batch, no block barrier)
        if (tid < 128) {
            const int wid = tid >> 5, lane = tid & 31;
            const int bb = wid;
            for (int job = lane; job < 36; job += 32) {
                int n = job / 6, m2 = job % 6;
                const float* qr = s.q2[bb * 6 + n];
                const float* kr = s.k2[bb * 6 + m2];
                float sc = 0.f;
                #pragma unroll
                for (int d = 0; d < 32; d++) sc += qr[d] * kr[d];
                s.p2[bb * 6 + n][m2] = sc * 0.17677669529663687f;
            }
            __syncwarp();
            if (lane < 6) {
                const int u = bb * 6 + lane;
                float mx = -1e30f;
                #pragma unroll
                for (int m2 = 0; m2 < 6; m2++) mx = fmaxf(mx, s.p2[u][m2]);
                float e[6], sum = 0.f;
                #pragma unroll
                for (int m2 = 0; m2 < 6; m2++) { e[m2] = expf(s.p2[u][m2] - mx); sum += e[m2]; }
                float inv = 1.f / sum;
                #pragma unroll
                for (int m2 = 0; m2 < 6; m2++) s.p2[u][m2] = e[m2] * inv;
            }
        }
        __syncthreads();   // b5: p2 ready

        // ---- phase F: hc = hn + p2@v2; blend; write state + history
        {
            const int u = tid & 31, jb = tid >> 5;
            if (u < 24) {
                const int bb = u / 6;
                const float m = masks[t * B_ + b0 + bb];
                const float bmu = s.bm[u];
                float pr[6];
                #pragma unroll
                for (int m2 = 0; m2 < 6; m2++) pr[m2] = s.p2[u][m2];
                for (int j = jb; j < 100; j += 20) {
                    float acc = s.hn[j][u];
                    #pragma unroll
                    for (int m2 = 0; m2 < 6; m2++) acc += pr[m2] * s.v2[bb * 6 + m2][j];
                    float res = (bmu > 0.5f) ? acc : (m * s.hb[j][u]);
                    s.hb[j][u] = res;
                    g_out[((size_t)t * B_ + b0 + bb) * NHID + (u % 6) * 100 + j] = res;
                }
            }
        }
    }

    __syncthreads();
    for (int i = tid; i < 2400; i += 640) {
        int bb = i / 600, j = i % 600;
        hT_out[(b0 + bb) * NHID + j] = s.hb[j % 100][bb * 6 + j / 100];
    }
}

// ---------------- launch ----------------
extern "C" void kernel_launch(void* const* d_in, const int* in_sizes, int n_in,
                              void* d_out, int out_size) {
    const float* input  = (const float*)d_in[0];
    const float* hidden = (const float*)d_in[1];
    const float* masks  = (const float*)d_in[2];
    const float* enc_W  = (const float*)d_in[3];
    const float* enc_b  = (const float*)d_in[4];
    const float* Wq     = (const float*)d_in[5];
    const float* Wk     = (const float*)d_in[6];
    const float* Wv     = (const float*)d_in[7];
    const float* Wx     = (const float*)d_in[8];
    const float* Wh     = (const float*)d_in[9];
    const float* gru_b  = (const float*)d_in[10];
    const float* Wq2    = (const float*)d_in[11];
    const float* Wk2    = (const float*)d_in[12];
    const float* Wv2    = (const float*)d_in[13];
    const float* dec_W  = (const float*)d_in[14];
    const float* dec_b  = (const float*)d_in[15];
    float* out = (float*)d_out;

    fold1<<<(513 * 404 + 255) / 256, 256>>>(enc_W, enc_b, Wk, Wv);
    fold2<<<(513 * 400 + 255) / 256, 256>>>(Wq, Wx);
    transposeW<<<(300 * 100 + 164 * 100 + 255) / 256, 256>>>(Wh, Wq2, Wk2, Wv2);

    gemm_wqkvx<<<dim3((400 + 127) / 128, TB / 128), 256>>>(input);

    static int smem_set = 0;
    int smem_bytes = (int)sizeof(StepSmem);
    if (!smem_set) {
        cudaFuncSetAttribute(steps_persistent,
                             cudaFuncAttributeMaxDynamicSharedMemorySize, smem_bytes);
        smem_set = 1;
    }

    float* hT_out    = out + DEC_OFF;
    float* bmask_out = out + DEC_OFF + B_ * NHID;
    steps_persistent<<<B_ / 4, 640, smem_bytes>>>(hidden, masks, gru_b, hT_out, bmask_out);

    gemm_dec<<<dim3((NTOK + 127) / 128, TB / 128), 256>>>(dec_W, dec_b, out);
}